// round 11
// baseline (speedup 1.0000x reference)
#include <cuda_runtime.h>
#include <cuda_fp16.h>
#include <cstdint>

// LorentzConv1d via single-pass fp16 mma.sync m16n8k16 (fp32 accum).
// Round 11: 256-thread CTAs (8 warps), MT=256, grid=512, 2 CTAs/SM
// (wave-tail smoothing + cross-CTA stage/compute overlap).
// Warp tile 32x64 and the K=320 row-major-pairing permutation carried from r10:
//   kb = 4*kIdx + jg; pair w of kb = (tap kIdx, channels 16jg+2w, 16jg+2w+1);
//   channel-0 (time) slots multiply B=0; t_resc is an fp32 epilogue rank-1 term.
// A tile xq = plain row-major fp16 (word c = channels {2c,2c+1}), warp-private.
//   XQS=36 -> A word bank = 4*q4 + s4 + const: conflict-free across the warp.

#define LLEN 8192
#define CIN  64
#define MT   256
#define XQS  36
#define WPRIV (36 * XQS)              // 1296 words per warp
#define WB4_OFF (8 * WPRIV)           // 10368 (16B aligned)
#define B_OFF   (WB4_OFF + 128)       // 10496 (16B aligned)
#define LGSTR   81                    // uint4 units per lane slot (20*4 + 1, odd)
#define B_UNITS (32 * LGSTR)          // 2592
#define SMEM_WORDS (B_OFF + B_UNITS * 4)  // 20864
#define SMEM_BYTES (SMEM_WORDS * 4)       // 83456

__device__ __forceinline__ uint32_t h2pack(float a, float b) {
    __half2 h = __floats2half2_rn(a, b);
    return *(uint32_t*)&h;
}
__device__ __forceinline__ void mma_f16(float* d, uint32_t a0, uint32_t a1,
                                        uint32_t a2, uint32_t a3,
                                        uint32_t b0, uint32_t b1) {
    asm volatile(
        "mma.sync.aligned.m16n8k16.row.col.f32.f16.f16.f32 "
        "{%0,%1,%2,%3}, {%4,%5,%6,%7}, {%8,%9}, {%0,%1,%2,%3};"
        : "+f"(d[0]), "+f"(d[1]), "+f"(d[2]), "+f"(d[3])
        : "r"(a0), "r"(a1), "r"(a2), "r"(a3), "r"(b0), "r"(b1));
}
// W weight for (kb, pair w, elem t): tap kIdx = kb>>2, channel 16*(kb&3)+2w+t
__device__ __forceinline__ float slotW(const float* __restrict__ W, int n,
                                       int kb, int w, int t) {
    int kIdx = kb >> 2;
    int jg   = kb & 3;
    int ch   = 16 * jg + 2 * w + t;
    if (ch == 0) return 0.f;          // time channel: zero in GEMM
    return W[(size_t)n * 316 + (ch - 1) * 5 + kIdx + 1];
}
__device__ __forceinline__ float tresc(const float* __restrict__ xb, int l) {
    float s = -4.0f;
#pragma unroll
    for (int k = 0; k < 5; k++) {
        int g = l - 2 + k;
        float t = ((unsigned)g < (unsigned)LLEN) ? xb[(size_t)g * CIN] : 1.0f;
        s = fmaf(t, t, s);
    }
    return sqrtf(s);
}

__global__ __launch_bounds__(256, 2)
void lorentz_f16_kernel(const float* __restrict__ x,
                        const float* __restrict__ W,
                        const float* __restrict__ bvec,
                        float* __restrict__ out)
{
    extern __shared__ uint32_t sm[];
    float4* wb4 = (float4*)(sm + WB4_OFF);
    uint4*  BQ4 = (uint4*)(sm + B_OFF);

    const int tid  = threadIdx.x;
    const int wid  = tid >> 5;
    const int lane = tid & 31;
    const int bidx = blockIdx.x >> 5;          // 32 tiles per batch
    const int l0   = (blockIdx.x & 31) << 8;   // 256 rows per tile
    const float* xb = x + (size_t)bidx * (LLEN * CIN);

    // ---- stage B (CTA-shared): unit (lg, kb, i) holds n = 16i+q4g and 16i+8+q4g ----
    for (int u = tid; u < 32 * 20 * 4; u += 256) {
        int i  = u & 3;
        int t2 = u >> 2;
        int kb = t2 % 20;
        int lg = t2 / 20;                      // 0..31
        int q4g = lg >> 2, s4g = lg & 3;
        int n0 = 16 * i + q4g;
        int n1 = n0 + 8;
        uint4 w;
        w.x = h2pack(slotW(W, n0, kb, s4g, 0),     slotW(W, n0, kb, s4g, 1));
        w.y = h2pack(slotW(W, n0, kb, s4g + 4, 0), slotW(W, n0, kb, s4g + 4, 1));
        w.z = h2pack(slotW(W, n1, kb, s4g, 0),     slotW(W, n1, kb, s4g, 1));
        w.w = h2pack(slotW(W, n1, kb, s4g + 4, 0), slotW(W, n1, kb, s4g + 4, 1));
        BQ4[lg * LGSTR + kb * 4 + i] = w;
    }
    // ---- fp32 time-weight + bias pairs ----
    if (tid < 32) {
        wb4[tid] = make_float4(W[(size_t)(2 * tid) * 316], bvec[2 * tid],
                               W[(size_t)(2 * tid + 1) * 316], bvec[2 * tid + 1]);
    }
    __syncthreads();   // the ONLY CTA-wide barrier

    // ---- warp-private xq staging: 36 rows, row-major fp16 ----
    const int wrow   = wid * 32;
    const int wpbase = wid * WPRIV;
    {
        const int gbase = l0 + wrow - 2;
#pragma unroll
        for (int j = 0; j < 18; j++) {
            int u  = j * 32 + lane;
            int r  = u >> 4, c4 = u & 15;
            int g  = gbase + r;
            float4 v;
            if ((unsigned)g < (unsigned)LLEN) v = *(const float4*)(xb + (size_t)g * CIN + c4 * 4);
            else { v = make_float4(0.f, 0.f, 0.f, 0.f); if (c4 == 0) v.x = 1.0f; }
            uint2 pw;
            pw.x = h2pack(v.x, v.y);
            pw.y = h2pack(v.z, v.w);
            *(uint2*)(sm + wpbase + r * XQS + c4 * 2) = pw;
        }
    }
    __syncwarp();

    // ---- mainloop: warp tile 32 rows x 64 cols, 20 k-blocks ----
    const int q4 = lane >> 2;
    const int s4 = lane & 3;
    const int bx = wpbase + q4 * XQS + s4;     // A base (word index)
    const int ub = (q4 * 4 + s4) * LGSTR;      // B base (uint4 index)

    float d[2][8][4];
#pragma unroll
    for (int m = 0; m < 2; m++)
#pragma unroll
        for (int nb = 0; nb < 8; nb++)
            d[m][nb][0] = d[m][nb][1] = d[m][nb][2] = d[m][nb][3] = 0.f;

#pragma unroll
    for (int kb = 0; kb < 20; kb++) {
        const int kIdx = kb >> 2;
        const int jg   = kb & 3;
        const int boff = kIdx * XQS + 8 * jg;

        uint4 b0 = BQ4[ub + kb * 4 + 0];
        uint4 b1 = BQ4[ub + kb * 4 + 1];
        uint4 b2 = BQ4[ub + kb * 4 + 2];
        uint4 b3 = BQ4[ub + kb * 4 + 3];

#pragma unroll
        for (int m = 0; m < 2; m++) {
            const int base0 = bx + boff + (16 * m) * XQS;
            const int base1 = base0 + 8 * XQS;
            uint32_t a0 = sm[base0];
            uint32_t a1 = sm[base1];
            uint32_t a2 = sm[base0 + 4];
            uint32_t a3 = sm[base1 + 4];
            mma_f16(d[m][0], a0, a1, a2, a3, b0.x, b0.y);
            mma_f16(d[m][1], a0, a1, a2, a3, b0.z, b0.w);
            mma_f16(d[m][2], a0, a1, a2, a3, b1.x, b1.y);
            mma_f16(d[m][3], a0, a1, a2, a3, b1.z, b1.w);
            mma_f16(d[m][4], a0, a1, a2, a3, b2.x, b2.y);
            mma_f16(d[m][5], a0, a1, a2, a3, b2.z, b2.w);
            mma_f16(d[m][6], a0, a1, a2, a3, b3.x, b3.y);
            mma_f16(d[m][7], a0, a1, a2, a3, b3.z, b3.w);
        }
    }

    // ---- epilogue: + W[:,0]*t_resc + b, Lorentz norm (in-warp over s4), store ----
#pragma unroll
    for (int m = 0; m < 2; m++) {
        const int ra = wrow + 16 * m + q4;
        const float tra = tresc(xb, l0 + ra);
        const float trb = tresc(xb, l0 + ra + 8);
        float ssa = 0.f, ssb = 0.f;
#pragma unroll
        for (int nb = 0; nb < 8; nb++) {
            float4 f4 = wb4[nb * 4 + s4];
            float y0 = fmaf(f4.x, tra, d[m][nb][0]) + f4.y;
            float y1 = fmaf(f4.z, tra, d[m][nb][1]) + f4.w;
            float y2 = fmaf(f4.x, trb, d[m][nb][2]) + f4.y;
            float y3 = fmaf(f4.z, trb, d[m][nb][3]) + f4.w;
            if (!(nb == 0 && s4 == 0)) {       // global col 0 excluded from the norm
                ssa = fmaf(y0, y0, ssa);
                ssb = fmaf(y2, y2, ssb);
            }
            ssa = fmaf(y1, y1, ssa);
            ssb = fmaf(y3, y3, ssb);
            d[m][nb][0] = y0; d[m][nb][1] = y1;
            d[m][nb][2] = y2; d[m][nb][3] = y3;
        }
        ssa += __shfl_xor_sync(0xffffffffu, ssa, 1);
        ssa += __shfl_xor_sync(0xffffffffu, ssa, 2);
        ssb += __shfl_xor_sync(0xffffffffu, ssb, 1);
        ssb += __shfl_xor_sync(0xffffffffu, ssb, 2);
        if (s4 == 0) {
            d[m][0][0] = sqrtf(ssa + 1.0f);
            d[m][0][2] = sqrtf(ssb + 1.0f);
        }

        const size_t oa = ((size_t)bidx * LLEN + (size_t)(l0 + ra)) * 64 + 2 * s4;
        const size_t ob = oa + 8 * 64;
#pragma unroll
        for (int nb = 0; nb < 8; nb++) {
            *(float2*)(out + oa + nb * 8) = make_float2(d[m][nb][0], d[m][nb][1]);
            *(float2*)(out + ob + nb * 8) = make_float2(d[m][nb][2], d[m][nb][3]);
        }
    }
}

extern "C" void kernel_launch(void* const* d_in, const int* in_sizes, int n_in,
                              void* d_out, int out_size)
{
    const float* x = (const float*)d_in[0];
    const float* W = (const float*)d_in[1];
    const float* b = (const float*)d_in[2];
    float* out = (float*)d_out;

    cudaFuncSetAttribute(lorentz_f16_kernel,
                         cudaFuncAttributeMaxDynamicSharedMemorySize, SMEM_BYTES);
    lorentz_f16_kernel<<<512, 256, SMEM_BYTES>>>(x, W, b, out);
}

// round 12
// speedup vs baseline: 1.2708x; 1.2708x over previous
#include <cuda_runtime.h>
#include <cuda_fp16.h>
#include <cstdint>

// LorentzConv1d via single-pass fp16 mma.sync m16n8k16 (fp32 accum).
// Round 12: persistent warps. grid=148 (one CTA/SM), 512 thr, 16 warps.
// 4096 independent warp-tiles of 32 rows; warp gw does t = gw, gw+2368.
// B staged once per SM. Warp-private A staging per tile (no CTA barrier in loop).
//
// K permutation (K=320, 20 kb x 8 pair-slots), row-major pairing (r10):
//   kb = 4*kIdx + jg; pair w of kb = (tap kIdx, channels 16jg+2w, 16jg+2w+1);
//   channel-0 (time) slots multiply B=0; t_resc is an fp32 epilogue rank-1 term.
// A tile xq = plain row-major fp16 (word c = channels {2c,2c+1}), warp-private.
//   XQS=36 -> A word bank = 4*q4 + s4 + const: conflict-free across the warp.

#define LLEN 8192
#define CIN  64
#define NSM  148
#define NWTOT (NSM * 16)              // 2368 warps
#define NTILES 4096                   // 16 batches x 256 tiles of 32 rows
#define XQS  36
#define WPRIV (36 * XQS)              // 1296 words per warp
#define WB4_OFF (16 * WPRIV)          // 20736 (16B aligned)
#define B_OFF   (WB4_OFF + 128)       // 20864 (16B aligned)
#define LGSTR   81                    // uint4 units per lane slot (20*4 + 1, odd)
#define B_UNITS (32 * LGSTR)          // 2592
#define SMEM_WORDS (B_OFF + B_UNITS * 4)  // 31232
#define SMEM_BYTES (SMEM_WORDS * 4)       // 124928

__device__ __forceinline__ uint32_t h2pack(float a, float b) {
    __half2 h = __floats2half2_rn(a, b);
    return *(uint32_t*)&h;
}
__device__ __forceinline__ void mma_f16(float* d, uint32_t a0, uint32_t a1,
                                        uint32_t a2, uint32_t a3,
                                        uint32_t b0, uint32_t b1) {
    asm volatile(
        "mma.sync.aligned.m16n8k16.row.col.f32.f16.f16.f32 "
        "{%0,%1,%2,%3}, {%4,%5,%6,%7}, {%8,%9}, {%0,%1,%2,%3};"
        : "+f"(d[0]), "+f"(d[1]), "+f"(d[2]), "+f"(d[3])
        : "r"(a0), "r"(a1), "r"(a2), "r"(a3), "r"(b0), "r"(b1));
}
// W weight for (kb, pair w, elem t): tap kIdx = kb>>2, channel 16*(kb&3)+2w+t
__device__ __forceinline__ float slotW(const float* __restrict__ W, int n,
                                       int kb, int w, int t) {
    int kIdx = kb >> 2;
    int jg   = kb & 3;
    int ch   = 16 * jg + 2 * w + t;
    if (ch == 0) return 0.f;          // time channel: zero in GEMM
    return W[(size_t)n * 316 + (ch - 1) * 5 + kIdx + 1];
}
__device__ __forceinline__ float tresc(const float* __restrict__ xb, int l) {
    float s = -4.0f;
#pragma unroll
    for (int k = 0; k < 5; k++) {
        int g = l - 2 + k;
        float t = ((unsigned)g < (unsigned)LLEN) ? xb[(size_t)g * CIN] : 1.0f;
        s = fmaf(t, t, s);
    }
    return sqrtf(s);
}

__global__ __launch_bounds__(512, 1)
void lorentz_f16_kernel(const float* __restrict__ x,
                        const float* __restrict__ W,
                        const float* __restrict__ bvec,
                        float* __restrict__ out)
{
    extern __shared__ uint32_t sm[];
    float4* wb4 = (float4*)(sm + WB4_OFF);
    uint4*  BQ4 = (uint4*)(sm + B_OFF);

    const int tid  = threadIdx.x;
    const int wid  = tid >> 5;
    const int lane = tid & 31;

    // ---- stage B (CTA-shared, ONCE per SM): unit (lg, kb, i) ----
    for (int u = tid; u < 32 * 20 * 4; u += 512) {
        int i  = u & 3;
        int t2 = u >> 2;
        int kb = t2 % 20;
        int lg = t2 / 20;                      // 0..31
        int q4g = lg >> 2, s4g = lg & 3;
        int n0 = 16 * i + q4g;
        int n1 = n0 + 8;
        uint4 w;
        w.x = h2pack(slotW(W, n0, kb, s4g, 0),     slotW(W, n0, kb, s4g, 1));
        w.y = h2pack(slotW(W, n0, kb, s4g + 4, 0), slotW(W, n0, kb, s4g + 4, 1));
        w.z = h2pack(slotW(W, n1, kb, s4g, 0),     slotW(W, n1, kb, s4g, 1));
        w.w = h2pack(slotW(W, n1, kb, s4g + 4, 0), slotW(W, n1, kb, s4g + 4, 1));
        BQ4[lg * LGSTR + kb * 4 + i] = w;
    }
    // ---- fp32 time-weight + bias pairs ----
    if (tid < 32) {
        wb4[tid] = make_float4(W[(size_t)(2 * tid) * 316], bvec[2 * tid],
                               W[(size_t)(2 * tid + 1) * 316], bvec[2 * tid + 1]);
    }
    __syncthreads();   // the ONLY CTA-wide barrier

    const int q4 = lane >> 2;
    const int s4 = lane & 3;
    const int wpbase = wid * WPRIV;
    const int bx = wpbase + q4 * XQS + s4;     // A base (word index)
    const int ub = (q4 * 4 + s4) * LGSTR;      // B base (uint4 index)
    const int gw = blockIdx.x * 16 + wid;      // global warp id

    // ---- persistent warp loop over 32-row tiles ----
    for (int t = gw; t < NTILES; t += NWTOT) {
        const int bidx = t >> 8;               // 256 tiles per batch
        const int l0   = (t & 255) << 5;
        const float* xb = x + (size_t)bidx * (LLEN * CIN);

        __syncwarp();   // previous tile's xq reads complete before overwrite

        // ---- warp-private xq staging: 36 rows (l0-2 .. l0+33), row-major fp16 ----
        {
            const int gbase = l0 - 2;
#pragma unroll
            for (int j = 0; j < 18; j++) {
                int u  = j * 32 + lane;
                int r  = u >> 4, c4 = u & 15;
                int g  = gbase + r;
                float4 v;
                if ((unsigned)g < (unsigned)LLEN) v = *(const float4*)(xb + (size_t)g * CIN + c4 * 4);
                else { v = make_float4(0.f, 0.f, 0.f, 0.f); if (c4 == 0) v.x = 1.0f; }
                uint2 pw;
                pw.x = h2pack(v.x, v.y);
                pw.y = h2pack(v.z, v.w);
                *(uint2*)(sm + wpbase + r * XQS + c4 * 2) = pw;
            }
        }
        __syncwarp();

        // ---- mainloop: warp tile 32 rows x 64 cols, 20 k-blocks ----
        float d[2][8][4];
#pragma unroll
        for (int m = 0; m < 2; m++)
#pragma unroll
            for (int nb = 0; nb < 8; nb++)
                d[m][nb][0] = d[m][nb][1] = d[m][nb][2] = d[m][nb][3] = 0.f;

#pragma unroll
        for (int kb = 0; kb < 20; kb++) {
            const int kIdx = kb >> 2;
            const int jg   = kb & 3;
            const int boff = kIdx * XQS + 8 * jg;

            uint4 b0 = BQ4[ub + kb * 4 + 0];
            uint4 b1 = BQ4[ub + kb * 4 + 1];
            uint4 b2 = BQ4[ub + kb * 4 + 2];
            uint4 b3 = BQ4[ub + kb * 4 + 3];

#pragma unroll
            for (int m = 0; m < 2; m++) {
                const int base0 = bx + boff + (16 * m) * XQS;
                const int base1 = base0 + 8 * XQS;
                uint32_t a0 = sm[base0];
                uint32_t a1 = sm[base1];
                uint32_t a2 = sm[base0 + 4];
                uint32_t a3 = sm[base1 + 4];
                mma_f16(d[m][0], a0, a1, a2, a3, b0.x, b0.y);
                mma_f16(d[m][1], a0, a1, a2, a3, b0.z, b0.w);
                mma_f16(d[m][2], a0, a1, a2, a3, b1.x, b1.y);
                mma_f16(d[m][3], a0, a1, a2, a3, b1.z, b1.w);
                mma_f16(d[m][4], a0, a1, a2, a3, b2.x, b2.y);
                mma_f16(d[m][5], a0, a1, a2, a3, b2.z, b2.w);
                mma_f16(d[m][6], a0, a1, a2, a3, b3.x, b3.y);
                mma_f16(d[m][7], a0, a1, a2, a3, b3.z, b3.w);
            }
        }

        // ---- epilogue: + W[:,0]*t_resc + b, Lorentz norm (in-warp over s4), store ----
#pragma unroll
        for (int m = 0; m < 2; m++) {
            const int ra = 16 * m + q4;
            const float tra = tresc(xb, l0 + ra);
            const float trb = tresc(xb, l0 + ra + 8);
            float ssa = 0.f, ssb = 0.f;
#pragma unroll
            for (int nb = 0; nb < 8; nb++) {
                float4 f4 = wb4[nb * 4 + s4];
                float y0 = fmaf(f4.x, tra, d[m][nb][0]) + f4.y;
                float y1 = fmaf(f4.z, tra, d[m][nb][1]) + f4.w;
                float y2 = fmaf(f4.x, trb, d[m][nb][2]) + f4.y;
                float y3 = fmaf(f4.z, trb, d[m][nb][3]) + f4.w;
                if (!(nb == 0 && s4 == 0)) {   // global col 0 excluded from the norm
                    ssa = fmaf(y0, y0, ssa);
                    ssb = fmaf(y2, y2, ssb);
                }
                ssa = fmaf(y1, y1, ssa);
                ssb = fmaf(y3, y3, ssb);
                d[m][nb][0] = y0; d[m][nb][1] = y1;
                d[m][nb][2] = y2; d[m][nb][3] = y3;
            }
            ssa += __shfl_xor_sync(0xffffffffu, ssa, 1);
            ssa += __shfl_xor_sync(0xffffffffu, ssa, 2);
            ssb += __shfl_xor_sync(0xffffffffu, ssb, 1);
            ssb += __shfl_xor_sync(0xffffffffu, ssb, 2);
            if (s4 == 0) {
                d[m][0][0] = sqrtf(ssa + 1.0f);
                d[m][0][2] = sqrtf(ssb + 1.0f);
            }

            const size_t oa = ((size_t)bidx * LLEN + (size_t)(l0 + ra)) * 64 + 2 * s4;
            const size_t ob = oa + 8 * 64;
#pragma unroll
            for (int nb = 0; nb < 8; nb++) {
                *(float2*)(out + oa + nb * 8) = make_float2(d[m][nb][0], d[m][nb][1]);
                *(float2*)(out + ob + nb * 8) = make_float2(d[m][nb][2], d[m][nb][3]);
            }
        }
    }
}

extern "C" void kernel_launch(void* const* d_in, const int* in_sizes, int n_in,
                              void* d_out, int out_size)
{
    const float* x = (const float*)d_in[0];
    const float* W = (const float*)d_in[1];
    const float* b = (const float*)d_in[2];
    float* out = (float*)d_out;

    cudaFuncSetAttribute(lorentz_f16_kernel,
                         cudaFuncAttributeMaxDynamicSharedMemorySize, SMEM_BYTES);
    lorentz_f16_kernel<<<NSM, 512, SMEM_BYTES>>>(x, W, b, out);
}